// round 14
// baseline (speedup 1.0000x reference)
#include <cuda_runtime.h>
#include <cuda_bf16.h>
#include <math.h>

#define NB      4
#define D_MODEL 256
#define HEADS   4
#define HEAD_DIM 64
#define NPTS    4096
#define TWO_D   512
#define L2E     1.4426950408889634f

// ---------------- scratch (device globals; no allocations allowed) ----------
__device__ __nv_bfloat16 g_Q[NB * D_MODEL * NPTS];
__device__ __nv_bfloat16 g_K[NB * D_MODEL * NPTS];
__device__ __nv_bfloat16 g_V[NB * D_MODEL * NPTS];
__device__ __nv_bfloat16 g_attn[NB * D_MODEL * NPTS];   // [b][h*64+d][n]
__device__ __nv_bfloat16 g_msghi[NB * D_MODEL * NPTS];
__device__ __nv_bfloat16 g_msglo[NB * D_MODEL * NPTS];
__device__ __nv_bfloat16 g_xhi[NB * D_MODEL * NPTS];
__device__ __nv_bfloat16 g_xlo[NB * D_MODEL * NPTS];
__device__ float g_h[NB * TWO_D * NPTS];
__device__ float g_scale[TWO_D];
__device__ float g_shift[TWO_D];
// converted weights
__device__ __nv_bfloat16 g_wq[D_MODEL * D_MODEL];
__device__ __nv_bfloat16 g_wk[D_MODEL * D_MODEL];
__device__ __nv_bfloat16 g_wv[D_MODEL * D_MODEL];
__device__ __nv_bfloat16 g_wm[D_MODEL * D_MODEL];
__device__ __nv_bfloat16 g_w1hi[TWO_D * TWO_D];
__device__ __nv_bfloat16 g_w1lo[TWO_D * TWO_D];
__device__ __nv_bfloat16 g_w2hi[D_MODEL * TWO_D];
__device__ __nv_bfloat16 g_w2lo[D_MODEL * TWO_D];

// ---------------------------------------------------------------------------
// helpers
// ---------------------------------------------------------------------------
__device__ __forceinline__ float ex2(float x) {
    float y; asm("ex2.approx.f32 %0, %1;" : "=f"(y) : "f"(x)); return y;
}
__device__ __forceinline__ unsigned packbf(float a, float b) {
    __nv_bfloat162 h = __floats2bfloat162_rn(a, b);
    return *(unsigned*)&h;
}
__device__ __forceinline__ float bf_rn(float v) {
    return __bfloat162float(__float2bfloat16_rn(v));
}
__device__ __forceinline__ void mma_bf16(float c[4],
    unsigned a0, unsigned a1, unsigned a2, unsigned a3,
    unsigned b0, unsigned b1)
{
    asm volatile(
        "mma.sync.aligned.m16n8k16.row.col.f32.bf16.bf16.f32 "
        "{%0,%1,%2,%3},{%4,%5,%6,%7},{%8,%9},{%0,%1,%2,%3};"
        : "+f"(c[0]), "+f"(c[1]), "+f"(c[2]), "+f"(c[3])
        : "r"(a0), "r"(a1), "r"(a2), "r"(a3), "r"(b0), "r"(b1));
}
__device__ __forceinline__ void ldsm_x4(
    unsigned &r0, unsigned &r1, unsigned &r2, unsigned &r3, unsigned addr)
{
    asm volatile("ldmatrix.sync.aligned.m8n8.x4.shared.b16 {%0,%1,%2,%3},[%4];"
        : "=r"(r0), "=r"(r1), "=r"(r2), "=r"(r3) : "r"(addr));
}
__device__ __forceinline__ void ldsm_x4_t(
    unsigned &r0, unsigned &r1, unsigned &r2, unsigned &r3, unsigned addr)
{
    asm volatile("ldmatrix.sync.aligned.m8n8.x4.trans.shared.b16 {%0,%1,%2,%3},[%4];"
        : "=r"(r0), "=r"(r1), "=r"(r2), "=r"(r3) : "r"(addr));
}

// ---------------------------------------------------------------------------
// one-shot converters (run once per replay; remove per-block redundancy)
// ---------------------------------------------------------------------------
__global__ void __launch_bounds__(256) cvt_bf16_kernel(
    const float* __restrict__ src, __nv_bfloat16* __restrict__ dst, int n4)
{
    int i = blockIdx.x * 256 + threadIdx.x;
    if (i < n4) {
        float4 v = ((const float4*)src)[i];
        uint2 p; p.x = packbf(v.x, v.y); p.y = packbf(v.z, v.w);
        ((uint2*)dst)[i] = p;
    }
}

__global__ void __launch_bounds__(256) split_bf16_kernel(
    const float* __restrict__ src,
    __nv_bfloat16* __restrict__ hi, __nv_bfloat16* __restrict__ lo, int n4)
{
    int i = blockIdx.x * 256 + threadIdx.x;
    if (i < n4) {
        float4 v = ((const float4*)src)[i];
        float hx = bf_rn(v.x), hy = bf_rn(v.y), hz = bf_rn(v.z), hw = bf_rn(v.w);
        uint2 ph, pl;
        ph.x = packbf(hx, hy); ph.y = packbf(hz, hw);
        pl.x = packbf(v.x - hx, v.y - hy);
        pl.y = packbf(v.z - hz, v.w - hw);
        ((uint2*)hi)[i] = ph;
        ((uint2*)lo)[i] = pl;
    }
}

// ---------------------------------------------------------------------------
// FAST bf16 GEMM (message path). 128x128 tile, 256 threads, K-chunk 64.
// W is pre-converted bf16 (raw uint4 loads).
//   perm:    X row for channel c = (c&3)*64 + (c>>2)            (merge)
//   inbf:    X is bf16 (raw copy)
//   outmode: 0 = fp32 out, 1 = bf16 out scaled by oscale, 2 = split hi/lo
// ---------------------------------------------------------------------------
#define WSTR 72
#define XSTR 136

__global__ void __launch_bounds__(256, 2) gemm_bf16(
    const void* __restrict__ A,
    const __nv_bfloat16* __restrict__ Wb, const float* __restrict__ bias,
    void* __restrict__ outv, void* __restrict__ outv2, int C, int O,
    int perm, int inbf, int outmode, float oscale)
{
    __shared__ __align__(16) __nv_bfloat16 Ws[128 * WSTR];
    __shared__ __align__(16) __nv_bfloat16 Xs[64 * XSTR];

    const int b  = blockIdx.z;
    const int o0 = blockIdx.y * 128;
    const int n0 = blockIdx.x * 128;
    const int t  = threadIdx.x;
    const int warp = t >> 5;
    const int lane = t & 31;
    const int w_o = (warp & 3) * 32;
    const int w_n = (warp >> 2) * 64;

    const unsigned ws_u = (unsigned)__cvta_generic_to_shared(Ws);
    const unsigned xs_u = (unsigned)__cvta_generic_to_shared(Xs);

    const int a_row  = lane & 15;
    const int a_col  = (lane >> 4) << 3;
    const int bt_row = (lane & 7) + ((lane >> 4) << 3);
    const int bt_col = ((lane >> 3) & 1) << 3;

    float acc[2][8][4];
#pragma unroll
    for (int mt = 0; mt < 2; mt++)
#pragma unroll
        for (int nt = 0; nt < 8; nt++)
#pragma unroll
            for (int j = 0; j < 4; j++) acc[mt][nt][j] = 0.f;

    for (int k0 = 0; k0 < C; k0 += 64) {
        // W tile: 128 rows x 64 k bf16, raw uint4 (8 chunks/row)
#pragma unroll
        for (int r = 0; r < 4; r++) {
            int idx = r * 256 + t;
            int oo = idx >> 3, kc = (idx & 7) * 8;
            *(uint4*)&Ws[oo * WSTR + kc] =
                *(const uint4*)&Wb[(size_t)(o0 + oo) * C + k0 + kc];
        }
        if (inbf) {
            const __nv_bfloat16* Ab = (const __nv_bfloat16*)A;
#pragma unroll
            for (int r = 0; r < 4; r++) {
                int idx = r * 256 + t;
                int kk = idx >> 4, nv = (idx & 15) * 8;
                int c = k0 + kk;
                int row = perm ? ((c & 3) * 64 + (c >> 2)) : c;
                *(uint4*)&Xs[kk * XSTR + nv] =
                    *(const uint4*)&Ab[((size_t)b * C + row) * NPTS + n0 + nv];
            }
        } else {
            const float* Af = (const float*)A;
#pragma unroll
            for (int r = 0; r < 8; r++) {
                int idx = r * 256 + t;
                int kk = idx >> 5, nv = (idx & 31) * 4;
                int c = k0 + kk;
                int row = perm ? ((c & 3) * 64 + (c >> 2)) : c;
                float4 v4 = *(const float4*)&Af[((size_t)b * C + row) * NPTS + n0 + nv];
                uint2 p; p.x = packbf(v4.x, v4.y); p.y = packbf(v4.z, v4.w);
                *(uint2*)&Xs[kk * XSTR + nv] = p;
            }
        }
        __syncthreads();

#pragma unroll
        for (int ks = 0; ks < 4; ks++) {
            unsigned a[2][4];
#pragma unroll
            for (int mt = 0; mt < 2; mt++) {
                unsigned addr = ws_u +
                    ((w_o + mt * 16 + a_row) * WSTR + ks * 16 + a_col) * 2;
                ldsm_x4(a[mt][0], a[mt][1], a[mt][2], a[mt][3], addr);
            }
#pragma unroll
            for (int np = 0; np < 4; np++) {
                unsigned b0, b1, b2, b3;
                unsigned addr = xs_u +
                    ((ks * 16 + bt_row) * XSTR + w_n + np * 16 + bt_col) * 2;
                ldsm_x4_t(b0, b1, b2, b3, addr);
#pragma unroll
                for (int mt = 0; mt < 2; mt++) {
                    mma_bf16(acc[mt][2 * np],     a[mt][0], a[mt][1], a[mt][2], a[mt][3], b0, b2);
                    mma_bf16(acc[mt][2 * np + 1], a[mt][0], a[mt][1], a[mt][2], a[mt][3], b1, b3);
                }
            }
        }
        __syncthreads();
    }

    const int g = lane >> 2, qt = lane & 3;
#pragma unroll
    for (int mt = 0; mt < 2; mt++) {
        int row0 = o0 + w_o + mt * 16 + g;
        int row1 = row0 + 8;
        float bs0 = bias[row0], bs1 = bias[row1];
        size_t p0 = ((size_t)b * O + row0) * NPTS + n0 + w_n + 2 * qt;
        size_t p1 = ((size_t)b * O + row1) * NPTS + n0 + w_n + 2 * qt;
        if (outmode == 1) {
            __nv_bfloat16* ob = (__nv_bfloat16*)outv;
#pragma unroll
            for (int nt = 0; nt < 8; nt++) {
                *(unsigned*)&ob[p0 + nt * 8] =
                    packbf((acc[mt][nt][0] + bs0) * oscale, (acc[mt][nt][1] + bs0) * oscale);
                *(unsigned*)&ob[p1 + nt * 8] =
                    packbf((acc[mt][nt][2] + bs1) * oscale, (acc[mt][nt][3] + bs1) * oscale);
            }
        } else if (outmode == 2) {
            __nv_bfloat16* oh = (__nv_bfloat16*)outv;
            __nv_bfloat16* ol = (__nv_bfloat16*)outv2;
#pragma unroll
            for (int nt = 0; nt < 8; nt++) {
                float v0 = acc[mt][nt][0] + bs0, v1 = acc[mt][nt][1] + bs0;
                float v2 = acc[mt][nt][2] + bs1, v3 = acc[mt][nt][3] + bs1;
                float h0 = bf_rn(v0), h1 = bf_rn(v1), h2 = bf_rn(v2), h3 = bf_rn(v3);
                *(unsigned*)&oh[p0 + nt * 8] = packbf(h0, h1);
                *(unsigned*)&ol[p0 + nt * 8] = packbf(v0 - h0, v1 - h1);
                *(unsigned*)&oh[p1 + nt * 8] = packbf(h2, h3);
                *(unsigned*)&ol[p1 + nt * 8] = packbf(v2 - h2, v3 - h3);
            }
        } else {
            float* of = (float*)outv;
#pragma unroll
            for (int nt = 0; nt < 8; nt++) {
                float2 v0, v1;
                v0.x = acc[mt][nt][0] + bs0; v0.y = acc[mt][nt][1] + bs0;
                v1.x = acc[mt][nt][2] + bs1; v1.y = acc[mt][nt][3] + bs1;
                *(float2*)&of[p0 + nt * 8] = v0;
                *(float2*)&of[p1 + nt * 8] = v1;
            }
        }
    }
}

// ---------------------------------------------------------------------------
// HIGH-PRECISION split-bf16 GEMM. W pre-split (bf16 hi/lo, raw loads).
//   mode 0: X pre-split concat (Ahi/Alo channels [0,Ca), Bhi/Blo rest)
//   mode 1: X fp32 + fused BN-affine+ReLU, split on the fly (mlp2)
// ---------------------------------------------------------------------------
#define SWSTR 40
#define SXSTR 136

__global__ void __launch_bounds__(256, 2) gemm_bf16_hp(
    const __nv_bfloat16* __restrict__ Whi_g, const __nv_bfloat16* __restrict__ Wlo_g,
    const __nv_bfloat16* __restrict__ Ahi, const __nv_bfloat16* __restrict__ Alo,
    const __nv_bfloat16* __restrict__ Bhi, const __nv_bfloat16* __restrict__ Blo,
    const float* __restrict__ Xf,
    const float* __restrict__ bias,
    const float* __restrict__ scale, const float* __restrict__ shift,
    float* __restrict__ out, int Ca, int Cb, int O, int mode)
{
    __shared__ __align__(16) __nv_bfloat16 Whi[128 * SWSTR];
    __shared__ __align__(16) __nv_bfloat16 Wlo[128 * SWSTR];
    __shared__ __align__(16) __nv_bfloat16 Xhi[32 * SXSTR];
    __shared__ __align__(16) __nv_bfloat16 Xlo[32 * SXSTR];

    const int b  = blockIdx.z;
    const int o0 = blockIdx.y * 128;
    const int n0 = blockIdx.x * 128;
    const int t  = threadIdx.x;
    const int warp = t >> 5;
    const int lane = t & 31;
    const int w_o = (warp & 3) * 32;
    const int w_n = (warp >> 2) * 64;
    const int C  = Ca + Cb;

    const unsigned whi_u = (unsigned)__cvta_generic_to_shared(Whi);
    const unsigned wlo_u = (unsigned)__cvta_generic_to_shared(Wlo);
    const unsigned xhi_u = (unsigned)__cvta_generic_to_shared(Xhi);
    const unsigned xlo_u = (unsigned)__cvta_generic_to_shared(Xlo);

    const int a_row  = lane & 15;
    const int a_col  = (lane >> 4) << 3;
    const int bt_row = (lane & 7) + ((lane >> 4) << 3);
    const int bt_col = ((lane >> 3) & 1) << 3;

    float acc[2][8][4];
#pragma unroll
    for (int mt = 0; mt < 2; mt++)
#pragma unroll
        for (int nt = 0; nt < 8; nt++)
#pragma unroll
            for (int j = 0; j < 4; j++) acc[mt][nt][j] = 0.f;

    for (int k0 = 0; k0 < C; k0 += 32) {
        // W tiles: 128 rows x 32 k, hi+lo, raw uint4 (4 chunks/row)
#pragma unroll
        for (int r = 0; r < 2; r++) {
            int idx = r * 256 + t;
            int oo = idx >> 2, kc = (idx & 3) * 8;
            size_t go = (size_t)(o0 + oo) * C + k0 + kc;
            *(uint4*)&Whi[oo * SWSTR + kc] = *(const uint4*)&Whi_g[go];
            *(uint4*)&Wlo[oo * SWSTR + kc] = *(const uint4*)&Wlo_g[go];
        }
        if (mode == 0) {
            // pre-split X: raw copies
#pragma unroll
            for (int r = 0; r < 2; r++) {
                int idx = r * 256 + t;
                int kk = idx >> 4, nc = (idx & 15) * 8;
                int c = k0 + kk;
                const __nv_bfloat16 *sh_, *sl_;
                if (c < Ca) {
                    sh_ = Ahi + ((size_t)b * Ca + c) * NPTS;
                    sl_ = Alo + ((size_t)b * Ca + c) * NPTS;
                } else {
                    sh_ = Bhi + ((size_t)b * Cb + (c - Ca)) * NPTS;
                    sl_ = Blo + ((size_t)b * Cb + (c - Ca)) * NPTS;
                }
                *(uint4*)&Xhi[kk * SXSTR + nc] = *(const uint4*)&sh_[n0 + nc];
                *(uint4*)&Xlo[kk * SXSTR + nc] = *(const uint4*)&sl_[n0 + nc];
            }
        } else {
            // fp32 + BN affine + ReLU + split
#pragma unroll
            for (int r = 0; r < 4; r++) {
                int idx = r * 256 + t;
                int kk = idx >> 5, nv = (idx & 31) * 4;
                int c = k0 + kk;
                float4 v4 = *(const float4*)&Xf[((size_t)b * C + c) * NPTS + n0 + nv];
                float sc = scale[c], sh = shift[c];
                v4.x = fmaxf(fmaf(v4.x, sc, sh), 0.f);
                v4.y = fmaxf(fmaf(v4.y, sc, sh), 0.f);
                v4.z = fmaxf(fmaf(v4.z, sc, sh), 0.f);
                v4.w = fmaxf(fmaf(v4.w, sc, sh), 0.f);
                float hx = bf_rn(v4.x), hy = bf_rn(v4.y), hz = bf_rn(v4.z), hw = bf_rn(v4.w);
                uint2 ph, pl;
                ph.x = packbf(hx, hy); ph.y = packbf(hz, hw);
                pl.x = packbf(v4.x - hx, v4.y - hy);
                pl.y = packbf(v4.z - hz, v4.w - hw);
                *(uint2*)&Xhi[kk * SXSTR + nv] = ph;
                *(uint2*)&Xlo[kk * SXSTR + nv] = pl;
            }
        }
        __syncthreads();

#pragma unroll
        for (int ks = 0; ks < 2; ks++) {
            unsigned ah[2][4], al[2][4];
#pragma unroll
            for (int mt = 0; mt < 2; mt++) {
                unsigned off = ((w_o + mt * 16 + a_row) * SWSTR + ks * 16 + a_col) * 2;
                ldsm_x4(ah[mt][0], ah[mt][1], ah[mt][2], ah[mt][3], whi_u + off);
                ldsm_x4(al[mt][0], al[mt][1], al[mt][2], al[mt][3], wlo_u + off);
            }
#pragma unroll
            for (int np = 0; np < 4; np++) {
                unsigned bh0, bh1, bh2, bh3, bl0, bl1, bl2, bl3;
                unsigned off = ((ks * 16 + bt_row) * SXSTR + w_n + np * 16 + bt_col) * 2;
                ldsm_x4_t(bh0, bh1, bh2, bh3, xhi_u + off);
                ldsm_x4_t(bl0, bl1, bl2, bl3, xlo_u + off);
#pragma unroll
                for (int mt = 0; mt < 2; mt++) {
                    mma_bf16(acc[mt][2 * np],     ah[mt][0], ah[mt][1], ah[mt][2], ah[mt][3], bh0, bh2);
                    mma_bf16(acc[mt][2 * np + 1], ah[mt][0], ah[mt][1], ah[mt][2], ah[mt][3], bh1, bh3);
                    mma_bf16(acc[mt][2 * np],     ah[mt][0], ah[mt][1], ah[mt][2], ah[mt][3], bl0, bl2);
                    mma_bf16(acc[mt][2 * np + 1], ah[mt][0], ah[mt][1], ah[mt][2], ah[mt][3], bl1, bl3);
                    mma_bf16(acc[mt][2 * np],     al[mt][0], al[mt][1], al[mt][2], al[mt][3], bh0, bh2);
                    mma_bf16(acc[mt][2 * np + 1], al[mt][0], al[mt][1], al[mt][2], al[mt][3], bh1, bh3);
                }
            }
        }
        __syncthreads();
    }

    const int g = lane >> 2, qt = lane & 3;
#pragma unroll
    for (int mt = 0; mt < 2; mt++) {
        int row0 = o0 + w_o + mt * 16 + g;
        int row1 = row0 + 8;
        float bs0 = bias[row0], bs1 = bias[row1];
        float* p0 = out + ((size_t)b * O + row0) * NPTS + n0 + w_n + 2 * qt;
        float* p1 = out + ((size_t)b * O + row1) * NPTS + n0 + w_n + 2 * qt;
#pragma unroll
        for (int nt = 0; nt < 8; nt++) {
            float2 v0, v1;
            v0.x = acc[mt][nt][0] + bs0; v0.y = acc[mt][nt][1] + bs0;
            v1.x = acc[mt][nt][2] + bs1; v1.y = acc[mt][nt][3] + bs1;
            *(float2*)&p0[nt * 8] = v0;
            *(float2*)&p1[nt * 8] = v1;
        }
    }
}

// ---------------------------------------------------------------------------
// Flash attention v3.1: 4 warps x 32 q-rows, halved ldsm traffic,
// fixed-max softmax. Prefetch staged K-then-V to halve peak prefetch
// registers and shorten live ranges (round-12 hit the 255-reg ceiling).
// ---------------------------------------------------------------------------
#define QSTR 136
#define KSTR 72
#define FA_Q_BYTES  (64 * QSTR * 2)
#define FA_KV_BYTES (64 * KSTR * 2)
#define FA_DSM (FA_Q_BYTES + 4 * FA_KV_BYTES)    // 54272

__global__ void __launch_bounds__(128, 2) flash_attn_bf16(
    const __nv_bfloat16* __restrict__ Q, const __nv_bfloat16* __restrict__ K,
    const __nv_bfloat16* __restrict__ V, __nv_bfloat16* __restrict__ Out)
{
    extern __shared__ __align__(16) char dsm[];
    __nv_bfloat16* Qs = (__nv_bfloat16*)dsm;
    __nv_bfloat16* Ksm = (__nv_bfloat16*)(dsm + FA_Q_BYTES);
    __nv_bfloat16* Vsm = (__nv_bfloat16*)(dsm + FA_Q_BYTES + 2 * FA_KV_BYTES);
    float* stage = (float*)dsm;

    const int n0   = blockIdx.x * 128;
    const int h    = blockIdx.y;
    const int b    = blockIdx.z;
    const int t    = threadIdx.x;
    const int warp = t >> 5;
    const int lane = t & 31;
    const int w32  = warp * 32;

    const unsigned qs_u = (unsigned)__cvta_generic_to_shared(Qs);
    const unsigned k0_u = (unsigned)__cvta_generic_to_shared(Ksm);
    const unsigned v0_u = (unsigned)__cvta_generic_to_shared(Vsm);

    const int qk_row = (lane & 7) + ((lane >> 4) << 3);
    const int qk_col = ((lane >> 3) & 1) << 3;
    const int v_row  = (lane & 7) + (((lane >> 3) & 1) << 3);
    const int v_col  = (lane >> 4) << 3;

    const __nv_bfloat16* Qb = Q + (size_t)b * D_MODEL * NPTS;
    const __nv_bfloat16* Kb = K + (size_t)b * D_MODEL * NPTS;
    const __nv_bfloat16* Vb = V + (size_t)b * D_MODEL * NPTS;

#pragma unroll
    for (int r = 0; r < 8; r++) {
        int idx = r * 128 + t;
        int dd = idx >> 4, c = idx & 15;
        uint4 v = *(const uint4*)&Qb[(size_t)(dd * HEADS + h) * NPTS + n0 + c * 8];
        *(uint4*)&Qs[dd * QSTR + c * 8] = v;
    }
#pragma unroll
    for (int r = 0; r < 4; r++) {
        int idx = r * 128 + t;
        int dd = idx >> 3, c = idx & 7;
        size_t go = (size_t)(dd * HEADS + h) * NPTS + c * 8;
        unsigned so = (dd * KSTR + c * 8) * 2;
        *(uint4*)((char*)Ksm + so) = *(const uint4*)&Kb[go];
        *(uint4*)((char*)Vsm + so) = *(const uint4*)&Vb[go];
    }
    __syncthreads();

    unsigned qf[2][4][4];
#pragma unroll
    for (int mt = 0; mt < 2; mt++)
#pragma unroll
        for (int kd = 0; kd < 4; kd++) {
            unsigned addr = qs_u +
                ((kd * 16 + qk_row) * QSTR + w32 + mt * 16 + qk_col) * 2;
            ldsm_x4_t(qf[mt][kd][0], qf[mt][kd][1], qf[mt][kd][2], qf[mt][kd][3], addr);
        }

    float l[2][2] = {{0.f, 0.f}, {0.f, 0.f}};
    float O_[2][8][4];
#pragma unroll
    for (int mt = 0; mt < 2; mt++)
#pragma unroll
        for (int i = 0; i < 8; i++)
#pragma unroll
            for (int j = 0; j < 4; j++) O_[mt][i][j] = 0.f;

    const int kv_dd[4] = { t >> 3, (128 + t) >> 3, (256 + t) >> 3, (384 + t) >> 3 };
    const int kv_c = t & 7;

    const int NT = NPTS / 64;
    for (int it = 0; it < NT; it++) {
        const int buf = it & 1;
        const unsigned kb_u = k0_u + buf * FA_KV_BYTES;
        const unsigned vb_u = v0_u + buf * FA_KV_BYTES;
        const bool has_next = (it + 1 < NT);
        const size_t m1 = (size_t)(it + 1) * 64;

        // ---- stage 1: prefetch next K (regs live only through S-phase)
        uint4 nk[4];
        if (has_next) {
#pragma unroll
            for (int r = 0; r < 4; r++)
                nk[r] = *(const uint4*)&Kb[(size_t)(kv_dd[r] * HEADS + h) * NPTS + m1 + kv_c * 8];
        }

        // ---- S = Q K^T
        float S[2][8][4];
#pragma unroll
        for (int mt = 0; mt < 2; mt++)
#pragma unroll
            for (int i = 0; i < 8; i++)
#pragma unroll
                for (int j = 0; j < 4; j++) S[mt][i][j] = 0.f;

#pragma unroll
        for (int kd = 0; kd < 4; kd++) {
#pragma unroll
            for (int np = 0; np < 4; np++) {
                unsigned b0, b1, b2, b3;
                unsigned addr = kb_u + ((kd * 16 + qk_row) * KSTR + np * 16 + qk_col) * 2;
                ldsm_x4_t(b0, b1, b2, b3, addr);
#pragma unroll
                for (int mt = 0; mt < 2; mt++) {
                    mma_bf16(S[mt][2 * np],     qf[mt][kd][0], qf[mt][kd][1], qf[mt][kd][2], qf[mt][kd][3], b0, b2);
                    mma_bf16(S[mt][2 * np + 1], qf[mt][kd][0], qf[mt][kd][1], qf[mt][kd][2], qf[mt][kd][3], b1, b3);
                }
            }
        }

        // ---- stash K; stage 2: prefetch next V
        uint4 nv[4];
        if (has_next) {
            char* kn = (char*)Ksm + (buf ^ 1) * FA_KV_BYTES;
#pragma unroll
            for (int r = 0; r < 4; r++)
                *(uint4*)(kn + (kv_dd[r] * KSTR + kv_c * 8) * 2) = nk[r];
#pragma unroll
            for (int r = 0; r < 4; r++)
                nv[r] = *(const uint4*)&Vb[(size_t)(kv_dd[r] * HEADS + h) * NPTS + m1 + kv_c * 8];
        }

        // ---- fixed-max softmax + pack
        unsigned pf[2][4][4];
#pragma unroll
        for (int mt = 0; mt < 2; mt++) {
#pragma unroll
            for (int nt = 0; nt < 8; nt++) {
                S[mt][nt][0] = ex2(S[mt][nt][0]);
                S[mt][nt][1] = ex2(S[mt][nt][1]);
                S[mt][nt][2] = ex2(S[mt][nt][2]);
                S[mt][nt][3] = ex2(S[mt][nt][3]);
                l[mt][0] += S[mt][nt][0] + S[mt][nt][1];
                l[mt][1] += S[mt][nt][2] + S[mt][nt][3];
            }
#pragma unroll
            for (int ks = 0; ks < 4; ks++) {
                pf[mt][ks][0] = packbf(S[mt][2 * ks][0],     S[mt][2 * ks][1]);
                pf[mt][ks][1] = packbf(S[mt][2 * ks][2],     S[mt][2 * ks][3]);
                pf[mt][ks][2] = packbf(S[mt][2 * ks + 1][0], S[mt][2 * ks + 1][1]);
                pf[mt][ks][3] = packbf(S[mt][2 * ks + 1][2], S[mt][2 * ks + 1][3]);
            }
        }

        // ---- O += P V
#pragma unroll
        for (int ks = 0; ks < 4; ks++) {
#pragma unroll
            for (int dp = 0; dp < 4; dp++) {
                unsigned b0, b1, b2, b3;
                unsigned addr = vb_u + ((dp * 16 + v_row) * KSTR + ks * 16 + v_col) * 2;
                ldsm_x4(b0, b1, b2, b3, addr);
#pragma unroll
                for (int mt = 0; mt < 2; mt++) {
                    mma_bf16(O_[mt][2 * dp],     pf[mt][ks][0], pf[mt][ks][1], pf[mt][ks][2], pf[mt][ks][3], b0, b2);
                    mma_bf16(O_[mt][2 * dp + 1], pf[mt][ks][0], pf[mt][ks][1], pf[mt][ks][2], pf[mt][ks][3], b1, b3);
                }
            }
        }

        // ---- stash V; barrier
        if (has_next) {
            char* vn = (char*)Vsm + (buf ^ 1) * FA_KV_BYTES;
#pragma unroll
            for (int r = 0; r < 4; r++)
                *(uint4*)(vn + (kv_dd[r] * KSTR + kv_c * 8) * 2) = nv[r];
        }
        __syncthreads();
    }

#pragma unroll
    for (int mt = 0; mt < 2; mt++) {
        l[mt][0] += __shfl_xor_sync(0xffffffffu, l[mt][0], 1);
        l[mt][0] += __shfl_xor_sync(0xffffffffu, l[mt][0], 2);
        l[mt][1] += __shfl_xor_sync(0xffffffffu, l[mt][1], 1);
        l[mt][1] += __shfl_xor_sync(0xffffffffu, l[mt][1], 2);
    }

    const int g = lane >> 2, qt = lane & 3;
#pragma unroll
    for (int mt = 0; mt < 2; mt++) {
        float inv0 = 1.f / l[mt][0], inv1 = 1.f / l[mt][1];
        int r0 = w32 + mt * 16 + g;
#pragma unroll
        for (int dt = 0; dt < 8; dt++) {
            stage[r0       * 65 + dt * 8 + 2 * qt]     = O_[mt][dt][0] * inv0;
            stage[r0       * 65 + dt * 8 + 2 * qt + 1] = O_[mt][dt][1] * inv0;
            stage[(r0 + 8) * 65 + dt * 8 + 2 * qt]     = O_[mt][dt][2] * inv1;
            stage[(r0 + 8) * 65 + dt * 8 + 2 * qt + 1] = O_[mt][dt][3] * inv1;
        }
    }
    __syncthreads();

    __nv_bfloat16* ob = Out + ((size_t)(b * HEADS + h) * HEAD_DIM) * NPTS + n0;
#pragma unroll
    for (int r = 0; r < 32; r++) {
        int idx = r * 128 + t;
        int d = idx >> 6, nn2 = (idx & 63) * 2;
        *(unsigned*)&ob[(size_t)d * NPTS + nn2] =
            packbf(stage[nn2 * 65 + d], stage[(nn2 + 1) * 65 + d]);
    }
}

// ---------------------------------------------------------------------------
// BN stats -> per-channel affine (scale, shift); biased variance like torch.
// ---------------------------------------------------------------------------
__global__ void __launch_bounds__(256) bn_stats_kernel(
    const float* __restrict__ hbuf, const float* __restrict__ gamma,
    const float* __restrict__ beta,
    float* __restrict__ scalep, float* __restrict__ shiftp)
{
    const int c = blockIdx.x;
    float s = 0.f, s2 = 0.f;
    for (int idx = threadIdx.x; idx < NB * NPTS; idx += 256) {
        int b = idx >> 12;
        int n = idx & (NPTS - 1);
        float v = hbuf[((size_t)b * TWO_D + c) * NPTS + n];
        s += v; s2 += v * v;
    }
    __shared__ float sh[256], sh2[256];
    sh[threadIdx.x] = s; sh2[threadIdx.x] = s2;
    __syncthreads();
    for (int st = 128; st > 0; st >>= 1) {
        if (threadIdx.x < st) {
            sh[threadIdx.x]  += sh[threadIdx.x + st];
            sh2[threadIdx.x] += sh2[threadIdx.x + st];
        }
        __syncthreads();
    }
    if (threadIdx.x == 0) {
        const float invn = 1.f / (float)(NB * NPTS);
        float mean = sh[0] * invn;
        float var  = sh2[0] * invn - mean * mean;
        float istd = rsqrtf(var + 1e-5f);
        float sc = gamma[c] * istd;
        scalep[c] = sc;
        shiftp[c] = beta[c] - mean * sc;
    }
}

// ---------------------------------------------------------------------------
extern "C" void kernel_launch(void* const* d_in, const int* in_sizes, int n_in,
                              void* d_out, int out_size)
{
    (void)in_sizes; (void)n_in; (void)out_size;

    const float* x       = (const float*)d_in[0];
    const float* src     = (const float*)d_in[1];
    const float* pq_w    = (const float*)d_in[2];
    const float* pq_b    = (const float*)d_in[3];
    const float* pk_w    = (const float*)d_in[4];
    const float* pk_b    = (const float*)d_in[5];
    const float* pv_w    = (const float*)d_in[6];
    const float* pv_b    = (const float*)d_in[7];
    const float* merge_w = (const float*)d_in[8];
    const float* merge_b = (const float*)d_in[9];
    const float* mlp1_w  = (const float*)d_in[10];
    const float* mlp1_b  = (const float*)d_in[11];
    const float* bn_g    = (const float*)d_in[12];
    const float* bn_b    = (const float*)d_in[13];
    const float* mlp2_w  = (const float*)d_in[14];
    const float* mlp2_b  = (const float*)d_in[15];
    float* out = (float*)d_out;

    __nv_bfloat16 *Qp, *Kp, *Vp, *Ap, *mhip, *mlop, *xhip, *xlop;
    __nv_bfloat16 *wq, *wk, *wv, *wm, *w1h, *w1l, *w2h, *w2l;
    float *Hp, *scalep, *shiftp;
    cudaGetSymbolAddress((void**)&Qp,     g_Q);
    cudaGetSymbolAddress((void**)&Kp,     g_K);
    cudaGetSymbolAddress((void**)&Vp,     g_V);
    cudaGetSymbolAddress((void**)&Ap,     g_attn);
    cudaGetSymbolAddress((void**)&mhip,   g_msghi);
    cudaGetSymbolAddress((void**)&mlop,   g_msglo);
    cudaGetSymbolAddress((void**)&xhip,   g_xhi);
    cudaGetSymbolAddress((void**)&xlop,   g_xlo);
    cudaGetSymbolAddress((void**)&Hp,     g_h);
    cudaGetSymbolAddress((void**)&scalep, g_scale);
    cudaGetSymbolAddress((void**)&shiftp, g_shift);
    cudaGetSymbolAddress((void**)&wq,     g_wq);
    cudaGetSymbolAddress((void**)&wk,     g_wk);
    cudaGetSymbolAddress((void**)&wv,     g_wv);
    cudaGetSymbolAddress((void**)&wm,     g_wm);
    cudaGetSymbolAddress((void**)&w1h,    g_w1hi);
    cudaGetSymbolAddress((void**)&w1l,    g_w1lo);
    cudaGetSymbolAddress((void**)&w2h,    g_w2hi);
    cudaGetSymbolAddress((void**)&w2l,    g_w2lo);

    cudaFuncSetAttribute(flash_attn_bf16,
                         cudaFuncAttributeMaxDynamicSharedMemorySize, FA_DSM);

    dim3 blk(256);
    dim3 g256(NPTS / 128, D_MODEL / 128, NB);
    dim3 g512(NPTS / 128, TWO_D / 128, NB);

    const float qsc = 0.125f * L2E;

    // ---- one-shot converters
    const int wn4 = D_MODEL * D_MODEL / 4;              // 16384
    cvt_bf16_kernel<<<wn4 / 256, blk>>>(pq_w,    wq, wn4);
    cvt_bf16_kernel<<<wn4 / 256, blk>>>(pk_w,    wk, wn4);
    cvt_bf16_kernel<<<wn4 / 256, blk>>>(pv_w,    wv, wn4);
    cvt_bf16_kernel<<<wn4 / 256, blk>>>(merge_w, wm, wn4);
    const int w1n4 = TWO_D * TWO_D / 4;                 // 65536
    const int w2n4 = D_MODEL * TWO_D / 4;               // 32768
    const int xn4  = NB * D_MODEL * NPTS / 4;           // 1048576
    split_bf16_kernel<<<w1n4 / 256, blk>>>(mlp1_w, w1h, w1l, w1n4);
    split_bf16_kernel<<<w2n4 / 256, blk>>>(mlp2_w, w2h, w2l, w2n4);
    split_bf16_kernel<<<xn4  / 256, blk>>>(x,      xhip, xlop, xn4);

    // ---- Q/K/V projections (bf16 W, fp32 X, bf16 out)
    gemm_bf16<<<g256, blk>>>(x,   wq, pq_b, Qp, nullptr, D_MODEL, D_MODEL, 0, 0, 1, qsc);
    gemm_bf16<<<g256, blk>>>(src, wk, pk_b, Kp, nullptr, D_MODEL, D_MODEL, 0, 0, 1, 1.0f);
    gemm_bf16<<<g256, blk>>>(src, wv, pv_b, Vp, nullptr, D_MODEL, D_MODEL, 0, 0, 1, 1.0f);

    // ---- multi-head attention
    flash_attn_bf16<<<dim3(NPTS / 128, HEADS, NB), dim3(128), FA_DSM>>>(Qp, Kp, Vp, Ap);

    // ---- merge: bf16 in (permuted rows), output split hi/lo for mlp1
    gemm_bf16<<<g256, blk>>>(Ap, wm, merge_b, mhip, mlop, D_MODEL, D_MODEL, 1, 1, 2, 1.0f);

    // ---- mlp1 on concat([x, message]) — pre-split inputs, raw copies
    gemm_bf16_hp<<<g512, blk>>>(w1h, w1l, xhip, xlop, mhip, mlop, nullptr,
                                mlp1_b, nullptr, nullptr,
                                Hp, D_MODEL, D_MODEL, TWO_D, 0);

    // ---- BN stats -> affine
    bn_stats_kernel<<<TWO_D, 256>>>(Hp, bn_g, bn_b, scalep, shiftp);

    // ---- mlp2 with fused BN affine + ReLU (fp32 X path)
    gemm_bf16_hp<<<g256, blk>>>(w2h, w2l, nullptr, nullptr, nullptr, nullptr, Hp,
                                mlp2_b, scalep, shiftp,
                                out, TWO_D, 0, D_MODEL, 1);
}

// round 15
// speedup vs baseline: 1.0115x; 1.0115x over previous
#include <cuda_runtime.h>
#include <cuda_bf16.h>
#include <math.h>

#define NB      4
#define D_MODEL 256
#define HEADS   4
#define HEAD_DIM 64
#define NPTS    4096
#define TWO_D   512
#define L2E     1.4426950408889634f

// ---------------- scratch (device globals; no allocations allowed) ----------
__device__ __nv_bfloat16 g_Q[NB * D_MODEL * NPTS];
__device__ __nv_bfloat16 g_K[NB * D_MODEL * NPTS];
__device__ __nv_bfloat16 g_V[NB * D_MODEL * NPTS];
__device__ __nv_bfloat16 g_attn[NB * D_MODEL * NPTS];   // [b][h*64+d][n]
__device__ __nv_bfloat16 g_msghi[NB * D_MODEL * NPTS];
__device__ __nv_bfloat16 g_msglo[NB * D_MODEL * NPTS];
__device__ __nv_bfloat16 g_xhi[NB * D_MODEL * NPTS];
__device__ __nv_bfloat16 g_xlo[NB * D_MODEL * NPTS];
__device__ float g_h[NB * TWO_D * NPTS];
__device__ float g_scale[TWO_D];
__device__ float g_shift[TWO_D];
// converted weights
__device__ __nv_bfloat16 g_wq[D_MODEL * D_MODEL];
__device__ __nv_bfloat16 g_wk[D_MODEL * D_MODEL];
__device__ __nv_bfloat16 g_wv[D_MODEL * D_MODEL];
__device__ __nv_bfloat16 g_wm[D_MODEL * D_MODEL];
__device__ __nv_bfloat16 g_w1hi[TWO_D * TWO_D];
__device__ __nv_bfloat16 g_w1lo[TWO_D * TWO_D];
__device__ __nv_bfloat16 g_w2hi[D_MODEL * TWO_D];
__device__ __nv_bfloat16 g_w2lo[D_MODEL * TWO_D];

// ---------------------------------------------------------------------------
// helpers
// ---------------------------------------------------------------------------
__device__ __forceinline__ unsigned packbf(float a, float b) {
    __nv_bfloat162 h = __floats2bfloat162_rn(a, b);
    return *(unsigned*)&h;
}
__device__ __forceinline__ float bf_rn(float v) {
    return __bfloat162float(__float2bfloat16_rn(v));
}
// Schraudolph fast exp2: one FFMA + one F2I; rel err <= ~3% (centered),
// fine here: P goes to bf16 mma (0.4% grain) and softmax-normalizes out.
__device__ __forceinline__ float ex2f(float x) {
    int i = (int)fmaf(x, 8388608.f, 1064987473.f);
    return __int_as_float(i);
}
__device__ __forceinline__ void mma_bf16(float c[4],
    unsigned a0, unsigned a1, unsigned a2, unsigned a3,
    unsigned b0, unsigned b1)
{
    asm volatile(
        "mma.sync.aligned.m16n8k16.row.col.f32.bf16.bf16.f32 "
        "{%0,%1,%2,%3},{%4,%5,%6,%7},{%8,%9},{%0,%1,%2,%3};"
        : "+f"(c[0]), "+f"(c[1]), "+f"(c[2]), "+f"(c[3])
        : "r"(a0), "r"(a1), "r"(a2), "r"(a3), "r"(b0), "r"(b1));
}
__device__ __forceinline__ void ldsm_x4(
    unsigned &r0, unsigned &r1, unsigned &r2, unsigned &r3, unsigned addr)
{
    asm volatile("ldmatrix.sync.aligned.m8n8.x4.shared.b16 {%0,%1,%2,%3},[%4];"
        : "=r"(r0), "=r"(r1), "=r"(r2), "=r"(r3) : "r"(addr));
}
__device__ __forceinline__ void ldsm_x4_t(
    unsigned &r0, unsigned &r1, unsigned &r2, unsigned &r3, unsigned addr)
{
    asm volatile("ldmatrix.sync.aligned.m8n8.x4.trans.shared.b16 {%0,%1,%2,%3},[%4];"
        : "=r"(r0), "=r"(r1), "=r"(r2), "=r"(r3) : "r"(addr));
}

// ---------------------------------------------------------------------------
// ONE consolidated weight converter (all 6 weight jobs in a single launch).
// float4 index ranges: [0,64K): 4x cvt 256x256; [64K,128K): w1 split;
// [128K,160K): w2 split. 640 blocks total.
// ---------------------------------------------------------------------------
__global__ void __launch_bounds__(256) cvt_weights_kernel(
    const float* __restrict__ pq, const float* __restrict__ pk,
    const float* __restrict__ pv, const float* __restrict__ pm,
    const float* __restrict__ w1, const float* __restrict__ w2,
    __nv_bfloat16* __restrict__ wq, __nv_bfloat16* __restrict__ wk,
    __nv_bfloat16* __restrict__ wv, __nv_bfloat16* __restrict__ wm,
    __nv_bfloat16* __restrict__ w1h, __nv_bfloat16* __restrict__ w1l,
    __nv_bfloat16* __restrict__ w2h, __nv_bfloat16* __restrict__ w2l)
{
    int i = blockIdx.x * 256 + threadIdx.x;
    if (i < 65536) {
        int sel = i >> 14, j = i & 16383;
        const float* s = (sel == 0) ? pq : (sel == 1) ? pk : (sel == 2) ? pv : pm;
        __nv_bfloat16* d = (sel == 0) ? wq : (sel == 1) ? wk : (sel == 2) ? wv : wm;
        float4 v = ((const float4*)s)[j];
        uint2 p; p.x = packbf(v.x, v.y); p.y = packbf(v.z, v.w);
        ((uint2*)d)[j] = p;
    } else {
        const float* s; __nv_bfloat16 *hi, *lo; int j;
        if (i < 131072) { j = i - 65536;  s = w1; hi = w1h; lo = w1l; }
        else            { j = i - 131072; s = w2; hi = w2h; lo = w2l; }
        float4 v = ((const float4*)s)[j];
        float hx = bf_rn(v.x), hy = bf_rn(v.y), hz = bf_rn(v.z), hw = bf_rn(v.w);
        uint2 ph, pl;
        ph.x = packbf(hx, hy); ph.y = packbf(hz, hw);
        pl.x = packbf(v.x - hx, v.y - hy);
        pl.y = packbf(v.z - hz, v.w - hw);
        ((uint2*)hi)[j] = ph;
        ((uint2*)lo)[j] = pl;
    }
}

__global__ void __launch_bounds__(256) split_bf16_kernel(
    const float* __restrict__ src,
    __nv_bfloat16* __restrict__ hi, __nv_bfloat16* __restrict__ lo, int n4)
{
    int i = blockIdx.x * 256 + threadIdx.x;
    if (i < n4) {
        float4 v = ((const float4*)src)[i];
        float hx = bf_rn(v.x), hy = bf_rn(v.y), hz = bf_rn(v.z), hw = bf_rn(v.w);
        uint2 ph, pl;
        ph.x = packbf(hx, hy); ph.y = packbf(hz, hw);
        pl.x = packbf(v.x - hx, v.y - hy);
        pl.y = packbf(v.z - hz, v.w - hw);
        ((uint2*)hi)[i] = ph;
        ((uint2*)lo)[i] = pl;
    }
}

// ---------------------------------------------------------------------------
// FAST bf16 GEMM (message path). 128x128 tile, 256 threads, K-chunk 64.
// W pre-converted bf16 (raw uint4 loads).
// ---------------------------------------------------------------------------
#define WSTR 72
#define XSTR 136

__global__ void __launch_bounds__(256, 2) gemm_bf16(
    const void* __restrict__ A,
    const __nv_bfloat16* __restrict__ Wb, const float* __restrict__ bias,
    void* __restrict__ outv, void* __restrict__ outv2, int C, int O,
    int perm, int inbf, int outmode, float oscale)
{
    __shared__ __align__(16) __nv_bfloat16 Ws[128 * WSTR];
    __shared__ __align__(16) __nv_bfloat16 Xs[64 * XSTR];

    const int b  = blockIdx.z;
    const int o0 = blockIdx.y * 128;
    const int n0 = blockIdx.x * 128;
    const int t  = threadIdx.x;
    const int warp = t >> 5;
    const int lane = t & 31;
    const int w_o = (warp & 3) * 32;
    const int w_n = (warp >> 2) * 64;

    const unsigned ws_u = (unsigned)__cvta_generic_to_shared(Ws);
    const unsigned xs_u = (unsigned)__cvta_generic_to_shared(Xs);

    const int a_row  = lane & 15;
    const int a_col  = (lane >> 4) << 3;
    const int bt_row = (lane & 7) + ((lane >> 4) << 3);
    const int bt_col = ((lane >> 3) & 1) << 3;

    float acc[2][8][4];
#pragma unroll
    for (int mt = 0; mt < 2; mt++)
#pragma unroll
        for (int nt = 0; nt < 8; nt++)
#pragma unroll
            for (int j = 0; j < 4; j++) acc[mt][nt][j] = 0.f;

    for (int k0 = 0; k0 < C; k0 += 64) {
#pragma unroll
        for (int r = 0; r < 4; r++) {
            int idx = r * 256 + t;
            int oo = idx >> 3, kc = (idx & 7) * 8;
            *(uint4*)&Ws[oo * WSTR + kc] =
                *(const uint4*)&Wb[(size_t)(o0 + oo) * C + k0 + kc];
        }
        if (inbf) {
            const __nv_bfloat16* Ab = (const __nv_bfloat16*)A;
#pragma unroll
            for (int r = 0; r < 4; r++) {
                int idx = r * 256 + t;
                int kk = idx >> 4, nv = (idx & 15) * 8;
                int c = k0 + kk;
                int row = perm ? ((c & 3) * 64 + (c >> 2)) : c;
                *(uint4*)&Xs[kk * XSTR + nv] =
                    *(const uint4*)&Ab[((size_t)b * C + row) * NPTS + n0 + nv];
            }
        } else {
            const float* Af = (const float*)A;
#pragma unroll
            for (int r = 0; r < 8; r++) {
                int idx = r * 256 + t;
                int kk = idx >> 5, nv = (idx & 31) * 4;
                int c = k0 + kk;
                int row = perm ? ((c & 3) * 64 + (c >> 2)) : c;
                float4 v4 = *(const float4*)&Af[((size_t)b * C + row) * NPTS + n0 + nv];
                uint2 p; p.x = packbf(v4.x, v4.y); p.y = packbf(v4.z, v4.w);
                *(uint2*)&Xs[kk * XSTR + nv] = p;
            }
        }
        __syncthreads();

#pragma unroll
        for (int ks = 0; ks < 4; ks++) {
            unsigned a[2][4];
#pragma unroll
            for (int mt = 0; mt < 2; mt++) {
                unsigned addr = ws_u +
                    ((w_o + mt * 16 + a_row) * WSTR + ks * 16 + a_col) * 2;
                ldsm_x4(a[mt][0], a[mt][1], a[mt][2], a[mt][3], addr);
            }
#pragma unroll
            for (int np = 0; np < 4; np++) {
                unsigned b0, b1, b2, b3;
                unsigned addr = xs_u +
                    ((ks * 16 + bt_row) * XSTR + w_n + np * 16 + bt_col) * 2;
                ldsm_x4_t(b0, b1, b2, b3, addr);
#pragma unroll
                for (int mt = 0; mt < 2; mt++) {
                    mma_bf16(acc[mt][2 * np],     a[mt][0], a[mt][1], a[mt][2], a[mt][3], b0, b2);
                    mma_bf16(acc[mt][2 * np + 1], a[mt][0], a[mt][1], a[mt][2], a[mt][3], b1, b3);
                }
            }
        }
        __syncthreads();
    }

    const int g = lane >> 2, qt = lane & 3;
#pragma unroll
    for (int mt = 0; mt < 2; mt++) {
        int row0 = o0 + w_o + mt * 16 + g;
        int row1 = row0 + 8;
        float bs0 = bias[row0], bs1 = bias[row1];
        size_t p0 = ((size_t)b * O + row0) * NPTS + n0 + w_n + 2 * qt;
        size_t p1 = ((size_t)b * O + row1) * NPTS + n0 + w_n + 2 * qt;
        if (outmode == 1) {
            __nv_bfloat16* ob = (__nv_bfloat16*)outv;
#pragma unroll
            for (int nt = 0; nt < 8; nt++) {
                *(unsigned*)&ob[p0 + nt * 8] =
                    packbf((acc[mt][nt][0] + bs0) * oscale, (acc[mt][nt][1] + bs0) * oscale);
                *(unsigned*)&ob[p1 + nt * 8] =
                    packbf((acc[mt][nt][2] + bs1) * oscale, (acc[mt][nt][3] + bs1) * oscale);
            }
        } else if (outmode == 2) {
            __nv_bfloat16* oh = (__nv_bfloat16*)outv;
            __nv_bfloat16* ol = (__nv_bfloat16*)outv2;
#pragma unroll
            for (int nt = 0; nt < 8; nt++) {
                float v0 = acc[mt][nt][0] + bs0, v1 = acc[mt][nt][1] + bs0;
                float v2 = acc[mt][nt][2] + bs1, v3 = acc[mt][nt][3] + bs1;
                float h0 = bf_rn(v0), h1 = bf_rn(v1), h2 = bf_rn(v2), h3 = bf_rn(v3);
                *(unsigned*)&oh[p0 + nt * 8] = packbf(h0, h1);
                *(unsigned*)&ol[p0 + nt * 8] = packbf(v0 - h0, v1 - h1);
                *(unsigned*)&oh[p1 + nt * 8] = packbf(h2, h3);
                *(unsigned*)&ol[p1 + nt * 8] = packbf(v2 - h2, v3 - h3);
            }
        } else {
            float* of = (float*)outv;
#pragma unroll
            for (int nt = 0; nt < 8; nt++) {
                float2 v0, v1;
                v0.x = acc[mt][nt][0] + bs0; v0.y = acc[mt][nt][1] + bs0;
                v1.x = acc[mt][nt][2] + bs1; v1.y = acc[mt][nt][3] + bs1;
                *(float2*)&of[p0 + nt * 8] = v0;
                *(float2*)&of[p1 + nt * 8] = v1;
            }
        }
    }
}

// ---------------------------------------------------------------------------
// HIGH-PRECISION split-bf16 GEMM. W pre-split (bf16 hi/lo, raw loads).
//   mode 0: X pre-split concat; mode 1: X fp32 + fused BN-affine+ReLU
// ---------------------------------------------------------------------------
#define SWSTR 40
#define SXSTR 136

__global__ void __launch_bounds__(256, 2) gemm_bf16_hp(
    const __nv_bfloat16* __restrict__ Whi_g, const __nv_bfloat16* __restrict__ Wlo_g,
    const __nv_bfloat16* __restrict__ Ahi, const __nv_bfloat16* __restrict__ Alo,
    const __nv_bfloat16* __restrict__ Bhi, const __nv_bfloat16* __restrict__ Blo,
    const float* __restrict__ Xf,
    const float* __restrict__ bias,
    const float* __restrict__ scale, const float* __restrict__ shift,
    float* __restrict__ out, int Ca, int Cb, int O, int mode)
{
    __shared__ __align__(16) __nv_bfloat16 Whi[128 * SWSTR];
    __shared__ __align__(16) __nv_bfloat16 Wlo[128 * SWSTR];
    __shared__ __align__(16) __nv_bfloat16 Xhi[32 * SXSTR];
    __shared__ __align__(16) __nv_bfloat16 Xlo[32 * SXSTR];

    const int b  = blockIdx.z;
    const int o0 = blockIdx.y * 128;
    const int n0 = blockIdx.x * 128;
    const int t  = threadIdx.x;
    const int warp = t >> 5;
    const int lane = t & 31;
    const int w_o = (warp & 3) * 32;
    const int w_n = (warp >> 2) * 64;
    const int C  = Ca + Cb;

    const unsigned whi_u = (unsigned)__cvta_generic_to_shared(Whi);
    const unsigned wlo_u = (unsigned)__cvta_generic_to_shared(Wlo);
    const unsigned xhi_u = (unsigned)__cvta_generic_to_shared(Xhi);
    const unsigned xlo_u = (unsigned)__cvta_generic_to_shared(Xlo);

    const int a_row  = lane & 15;
    const int a_col  = (lane >> 4) << 3;
    const int bt_row = (lane & 7) + ((lane >> 4) << 3);
    const int bt_col = ((lane >> 3) & 1) << 3;

    float acc[2][8][4];
#pragma unroll
    for (int mt = 0; mt < 2; mt++)
#pragma unroll
        for (int nt = 0; nt < 8; nt++)
#pragma unroll
            for (int j = 0; j < 4; j++) acc[mt][nt][j] = 0.f;

    for (int k0 = 0; k0 < C; k0 += 32) {
#pragma unroll
        for (int r = 0; r < 2; r++) {
            int idx = r * 256 + t;
            int oo = idx >> 2, kc = (idx & 3) * 8;
            size_t go = (size_t)(o0 + oo) * C + k0 + kc;
            *(uint4*)&Whi[oo * SWSTR + kc] = *(const uint4*)&Whi_g[go];
            *(uint4*)&Wlo[oo * SWSTR + kc] = *(const uint4*)&Wlo_g[go];
        }
        if (mode == 0) {
#pragma unroll
            for (int r = 0; r < 2; r++) {
                int idx = r * 256 + t;
                int kk = idx >> 4, nc = (idx & 15) * 8;
                int c = k0 + kk;
                const __nv_bfloat16 *sh_, *sl_;
                if (c < Ca) {
                    sh_ = Ahi + ((size_t)b * Ca + c) * NPTS;
                    sl_ = Alo + ((size_t)b * Ca + c) * NPTS;
                } else {
                    sh_ = Bhi + ((size_t)b * Cb + (c - Ca)) * NPTS;
                    sl_ = Blo + ((size_t)b * Cb + (c - Ca)) * NPTS;
                }
                *(uint4*)&Xhi[kk * SXSTR + nc] = *(const uint4*)&sh_[n0 + nc];
                *(uint4*)&Xlo[kk * SXSTR + nc] = *(const uint4*)&sl_[n0 + nc];
            }
        } else {
#pragma unroll
            for (int r = 0; r < 4; r++) {
                int idx = r * 256 + t;
                int kk = idx >> 5, nv = (idx & 31) * 4;
                int c = k0 + kk;
                float4 v4 = *(const float4*)&Xf[((size_t)b * C + c) * NPTS + n0 + nv];
                float sc = scale[c], sh = shift[c];
                v4.x = fmaxf(fmaf(v4.x, sc, sh), 0.f);
                v4.y = fmaxf(fmaf(v4.y, sc, sh), 0.f);
                v4.z = fmaxf(fmaf(v4.z, sc, sh), 0.f);
                v4.w = fmaxf(fmaf(v4.w, sc, sh), 0.f);
                float hx = bf_rn(v4.x), hy = bf_rn(v4.y), hz = bf_rn(v4.z), hw = bf_rn(v4.w);
                uint2 ph, pl;
                ph.x = packbf(hx, hy); ph.y = packbf(hz, hw);
                pl.x = packbf(v4.x - hx, v4.y - hy);
                pl.y = packbf(v4.z - hz, v4.w - hw);
                *(uint2*)&Xhi[kk * SXSTR + nv] = ph;
                *(uint2*)&Xlo[kk * SXSTR + nv] = pl;
            }
        }
        __syncthreads();

#pragma unroll
        for (int ks = 0; ks < 2; ks++) {
            unsigned ah[2][4], al[2][4];
#pragma unroll
            for (int mt = 0; mt < 2; mt++) {
                unsigned off = ((w_o + mt * 16 + a_row) * SWSTR + ks * 16 + a_col) * 2;
                ldsm_x4(ah[mt][0], ah[mt][1], ah[mt][2], ah[mt][3], whi_u + off);
                ldsm_x4(al[mt][0], al[mt][1], al[mt][2], al[mt][3], wlo_u + off);
            }
#pragma unroll
            for (int np = 0; np < 4; np++) {
                unsigned bh0, bh1, bh2, bh3, bl0, bl1, bl2, bl3;
                unsigned off = ((ks * 16 + bt_row) * SXSTR + w_n + np * 16 + bt_col) * 2;
                ldsm_x4_t(bh0, bh1, bh2, bh3, xhi_u + off);
                ldsm_x4_t(bl0, bl1, bl2, bl3, xlo_u + off);
#pragma unroll
                for (int mt = 0; mt < 2; mt++) {
                    mma_bf16(acc[mt][2 * np],     ah[mt][0], ah[mt][1], ah[mt][2], ah[mt][3], bh0, bh2);
                    mma_bf16(acc[mt][2 * np + 1], ah[mt][0], ah[mt][1], ah[mt][2], ah[mt][3], bh1, bh3);
                    mma_bf16(acc[mt][2 * np],     ah[mt][0], ah[mt][1], ah[mt][2], ah[mt][3], bl0, bl2);
                    mma_bf16(acc[mt][2 * np + 1], ah[mt][0], ah[mt][1], ah[mt][2], ah[mt][3], bl1, bl3);
                    mma_bf16(acc[mt][2 * np],     al[mt][0], al[mt][1], al[mt][2], al[mt][3], bh0, bh2);
                    mma_bf16(acc[mt][2 * np + 1], al[mt][0], al[mt][1], al[mt][2], al[mt][3], bh1, bh3);
                }
            }
        }
        __syncthreads();
    }

    const int g = lane >> 2, qt = lane & 3;
#pragma unroll
    for (int mt = 0; mt < 2; mt++) {
        int row0 = o0 + w_o + mt * 16 + g;
        int row1 = row0 + 8;
        float bs0 = bias[row0], bs1 = bias[row1];
        float* p0 = out + ((size_t)b * O + row0) * NPTS + n0 + w_n + 2 * qt;
        float* p1 = out + ((size_t)b * O + row1) * NPTS + n0 + w_n + 2 * qt;
#pragma unroll
        for (int nt = 0; nt < 8; nt++) {
            float2 v0, v1;
            v0.x = acc[mt][nt][0] + bs0; v0.y = acc[mt][nt][1] + bs0;
            v1.x = acc[mt][nt][2] + bs1; v1.y = acc[mt][nt][3] + bs1;
            *(float2*)&p0[nt * 8] = v0;
            *(float2*)&p1[nt * 8] = v1;
        }
    }
}

// ---------------------------------------------------------------------------
// Flash attention v3.2: 4 warps x 32 q-rows, staged K/V prefetch,
// fixed-max softmax with SCHRAUDOLPH exp2 (FFMA+F2I, no MUFU) and
// PRMT-based bf16 packing (P bf16 bits = top 16 of the exp2 bits).
// ---------------------------------------------------------------------------
#define QSTR 136
#define KSTR 72
#define FA_Q_BYTES  (64 * QSTR * 2)
#define FA_KV_BYTES (64 * KSTR * 2)
#define FA_DSM (FA_Q_BYTES + 4 * FA_KV_BYTES)    // 54272

__global__ void __launch_bounds__(128, 2) flash_attn_bf16(
    const __nv_bfloat16* __restrict__ Q, const __nv_bfloat16* __restrict__ K,
    const __nv_bfloat16* __restrict__ V, __nv_bfloat16* __restrict__ Out)
{
    extern __shared__ __align__(16) char dsm[];
    __nv_bfloat16* Qs = (__nv_bfloat16*)dsm;
    __nv_bfloat16* Ksm = (__nv_bfloat16*)(dsm + FA_Q_BYTES);
    __nv_bfloat16* Vsm = (__nv_bfloat16*)(dsm + FA_Q_BYTES + 2 * FA_KV_BYTES);
    float* stage = (float*)dsm;

    const int n0   = blockIdx.x * 128;
    const int h    = blockIdx.y;
    const int b    = blockIdx.z;
    const int t    = threadIdx.x;
    const int warp = t >> 5;
    const int lane = t & 31;
    const int w32  = warp * 32;

    const unsigned qs_u = (unsigned)__cvta_generic_to_shared(Qs);
    const unsigned k0_u = (unsigned)__cvta_generic_to_shared(Ksm);
    const unsigned v0_u = (unsigned)__cvta_generic_to_shared(Vsm);

    const int qk_row = (lane & 7) + ((lane >> 4) << 3);
    const int qk_col = ((lane >> 3) & 1) << 3;
    const int v_row  = (lane & 7) + (((lane >> 3) & 1) << 3);
    const int v_col  = (lane >> 4) << 3;

    const __nv_bfloat16* Qb = Q + (size_t)b * D_MODEL * NPTS;
    const __nv_bfloat16* Kb = K + (size_t)b * D_MODEL * NPTS;
    const __nv_bfloat16* Vb = V + (size_t)b * D_MODEL * NPTS;

#pragma unroll
    for (int r = 0; r < 8; r++) {
        int idx = r * 128 + t;
        int dd = idx >> 4, c = idx & 15;
        uint4 v = *(const uint4*)&Qb[(size_t)(dd * HEADS + h) * NPTS + n0 + c * 8];
        *(uint4*)&Qs[dd * QSTR + c * 8] = v;
    }
#pragma unroll
    for (int r = 0; r < 4; r++) {
        int idx = r * 128 + t;
        int dd = idx >> 3, c = idx & 7;
        size_t go = (size_t)(dd * HEADS + h) * NPTS + c * 8;
        unsigned so = (dd * KSTR + c * 8) * 2;
        *(uint4*)((char*)Ksm + so) = *(const uint4*)&Kb[go];
        *(uint4*)((char*)Vsm + so) = *(const uint4*)&Vb[go];
    }
    __syncthreads();

    unsigned qf[2][4][4];
#pragma unroll
    for (int mt = 0; mt < 2; mt++)
#pragma unroll
        for (int kd = 0; kd < 4; kd++) {
            unsigned addr = qs_u +
                ((kd * 16 + qk_row) * QSTR + w32 + mt * 16 + qk_col) * 2;
            ldsm_x4_t(qf[mt][kd][0], qf[mt][kd][1], qf[mt][kd][2], qf[mt][kd][3], addr);
        }

    float l[2][2] = {{0.f, 0.f}, {0.f, 0.f}};
    float O_[2][8][4];
#pragma unroll
    for (int mt = 0; mt < 2; mt++)
#pragma unroll
        for (int i = 0; i < 8; i++)
#pragma unroll
            for (int j = 0; j < 4; j++) O_[mt][i][j] = 0.f;

    const int kv_dd[4] = { t >> 3, (128 + t) >> 3, (256 + t) >> 3, (384 + t) >> 3 };
    const int kv_c = t & 7;

    const int NT = NPTS / 64;
    for (int it = 0; it < NT; it++) {
        const int buf = it & 1;
        const unsigned kb_u = k0_u + buf * FA_KV_BYTES;
        const unsigned vb_u = v0_u + buf * FA_KV_BYTES;
        const bool has_next = (it + 1 < NT);
        const size_t m1 = (size_t)(it + 1) * 64;

        uint4 nk[4];
        if (has_next) {
#pragma unroll
            for (int r = 0; r < 4; r++)
                nk[r] = *(const uint4*)&Kb[(size_t)(kv_dd[r] * HEADS + h) * NPTS + m1 + kv_c * 8];
        }

        // ---- S = Q K^T
        float S[2][8][4];
#pragma unroll
        for (int mt = 0; mt < 2; mt++)
#pragma unroll
            for (int i = 0; i < 8; i++)
#pragma unroll
                for (int j = 0; j < 4; j++) S[mt][i][j] = 0.f;

#pragma unroll
        for (int kd = 0; kd < 4; kd++) {
#pragma unroll
            for (int np = 0; np < 4; np++) {
                unsigned b0, b1, b2, b3;
                unsigned addr = kb_u + ((kd * 16 + qk_row) * KSTR + np * 16 + qk_col) * 2;
                ldsm_x4_t(b0, b1, b2, b3, addr);
#pragma unroll
                for (int mt = 0; mt < 2; mt++) {
                    mma_bf16(S[mt][2 * np],     qf[mt][kd][0], qf[mt][kd][1], qf[mt][kd][2], qf[mt][kd][3], b0, b2);
                    mma_bf16(S[mt][2 * np + 1], qf[mt][kd][0], qf[mt][kd][1], qf[mt][kd][2], qf[mt][kd][3], b1, b3);
                }
            }
        }

        uint4 nv[4];
        if (has_next) {
            char* kn = (char*)Ksm + (buf ^ 1) * FA_KV_BYTES;
#pragma unroll
            for (int r = 0; r < 4; r++)
                *(uint4*)(kn + (kv_dd[r] * KSTR + kv_c * 8) * 2) = nk[r];
#pragma unroll
            for (int r = 0; r < 4; r++)
                nv[r] = *(const uint4*)&Vb[(size_t)(kv_dd[r] * HEADS + h) * NPTS + m1 + kv_c * 8];
        }

        // ---- fixed-max softmax via Schraudolph exp2; PRMT pack to bf16x2
        unsigned pf[2][4][4];
#pragma unroll
        for (int mt = 0; mt < 2; mt++) {
#pragma unroll
            for (int nt = 0; nt < 8; nt++) {
                S[mt][nt][0] = ex2f(S[mt][nt][0]);
                S[mt][nt][1] = ex2f(S[mt][nt][1]);
                S[mt][nt][2] = ex2f(S[mt][nt][2]);
                S[mt][nt][3] = ex2f(S[mt][nt][3]);
                l[mt][0] += S[mt][nt][0] + S[mt][nt][1];
                l[mt][1] += S[mt][nt][2] + S[mt][nt][3];
            }
#pragma unroll
            for (int ks = 0; ks < 4; ks++) {
                pf[mt][ks][0] = __byte_perm(__float_as_int(S[mt][2 * ks][0]),
                                            __float_as_int(S[mt][2 * ks][1]), 0x7632);
                pf[mt][ks][1] = __byte_perm(__float_as_int(S[mt][2 * ks][2]),
                                            __float_as_int(S[mt][2 * ks][3]), 0x7632);
                pf[mt][ks][2] = __byte_perm(__float_as_int(S[mt][2 * ks + 1][0]),
                                            __float_as_int(S[mt][2 * ks + 1][1]), 0x7632);
                pf[mt][ks][3] = __byte_perm(__float_as_int(S[mt][2 * ks + 1][2]),
                                            __float_as_int(S[mt][2 * ks + 1][3]), 0x7632);
            }
        }

        // ---- O += P V
#pragma unroll
        for (int ks = 0; ks < 4; ks++) {
#pragma unroll
            for (int dp = 0; dp < 4; dp++) {
                unsigned b0, b1, b2, b3;
                unsigned addr = vb_u + ((dp * 16 + v_row) * KSTR + ks * 16 + v_col) * 2;
                ldsm_x4(b0, b1, b2, b3, addr);
#pragma unroll
                for (int mt = 0; mt < 2; mt++) {
                    mma_bf16(O_[mt][2 * dp],     pf[mt][ks][0], pf[mt][ks][1], pf[mt][ks][2], pf[mt][ks][3], b0, b2);
                    mma_bf16(O_[mt][2 * dp + 1], pf[mt][ks][0], pf[mt][ks][1], pf[mt][ks][2], pf[mt][ks][3], b1, b3);
                }
            }
        }

        if (has_next) {
            char* vn = (char*)Vsm + (buf ^ 1) * FA_KV_BYTES;
#pragma unroll
            for (int r = 0; r < 4; r++)
                *(uint4*)(vn + (kv_dd[r] * KSTR + kv_c * 8) * 2) = nv[r];
        }
        __syncthreads();
    }

#pragma unroll
    for (int mt = 0; mt < 2; mt++) {
        l[mt][0] += __shfl_xor_sync(0xffffffffu, l[mt][0], 1);
        l[mt][0] += __shfl_xor_sync(0xffffffffu, l[mt][0], 2);
        l[mt][1] += __shfl_xor_sync(0xffffffffu, l[mt][1], 1);
        l[mt][1] += __shfl_xor_sync(0xffffffffu, l[mt][1], 2);
    }

    const int g = lane >> 2, qt = lane & 3;
#pragma unroll
    for (int mt = 0; mt < 2; mt++) {
        float inv0 = 1.f / l[mt][0], inv1 = 1.f / l[mt][1];
        int r0 = w32 + mt * 16 + g;
#pragma unroll
        for (int dt = 0; dt < 8; dt++) {
            stage[r0       * 65 + dt * 8 + 2 * qt]     = O_[mt][dt][0] * inv0;
            stage[r0       * 65 + dt * 8 + 2 * qt + 1] = O_[mt][dt][1] * inv0;
            stage[(r0 + 8) * 65 + dt * 8 + 2 * qt]     = O_[mt][dt][2] * inv1;
            stage[(r0 + 8) * 65 + dt * 8 + 2 * qt + 1] = O_[mt][dt][3] * inv1;
        }
    }
    __syncthreads();

    __nv_bfloat16* ob = Out + ((size_t)(b * HEADS + h) * HEAD_DIM) * NPTS + n0;
#pragma unroll
    for (int r = 0; r < 32; r++) {
        int idx = r * 128 + t;
        int d = idx >> 6, nn2 = (idx & 63) * 2;
        *(unsigned*)&ob[(size_t)d * NPTS + nn2] =
            packbf(stage[nn2 * 65 + d], stage[(nn2 + 1) * 65 + d]);
    }
}

// ---------------------------------------------------------------------------
// BN stats -> per-channel affine (scale, shift); biased variance like torch.
// ---------------------------------------------------------------------------
__global__ void __launch_bounds__(256) bn_stats_kernel(
    const float* __restrict__ hbuf, const float* __restrict__ gamma,
    const float* __restrict__ beta,
    float* __restrict__ scalep, float* __restrict__ shiftp)
{
    const int c = blockIdx.x;
    float s = 0.f, s2 = 0.f;
    for (int idx = threadIdx.x; idx < NB * NPTS; idx += 256) {
        int b = idx >> 12;
        int n = idx & (NPTS - 1);
        float v = hbuf[((size_t)b * TWO_D + c) * NPTS + n];
        s += v; s2 += v * v;
    }
    __shared__ float sh[256], sh2[256];
    sh[threadIdx.x] = s; sh2[threadIdx.x] = s2;
    __syncthreads();
    for (int st = 128; st > 0; st >>= 1) {
        if (threadIdx.x < st) {
            sh[threadIdx.x]  += sh[threadIdx.x + st];
            sh2[threadIdx.x] += sh2[threadIdx.x + st];
        }
        __syncthreads();
    }
    if (threadIdx.x == 0) {
        const float invn = 1.f / (float)(NB * NPTS);
        float mean = sh[0] * invn;
        float var  = sh2[0] * invn - mean * mean;
        float istd = rsqrtf(var + 1e-5f);
        float sc = gamma[c] * istd;
        scalep[c] = sc;
        shiftp[c] = beta[c] - mean * sc;
    }
}

// ---------------------------------------------------------------------------
extern "C" void kernel_launch(void* const* d_in, const int* in_sizes, int n_in,
                              void* d_out, int out_size)
{
    (void)in_sizes; (void)n_in; (void)out_size;

    const float* x       = (const float*)d_in[0];
    const float* src     = (const float*)d_in[1];
    const float* pq_w    = (const float*)d_in[2];
    const float* pq_b    = (const float*)d_in[3];
    const float* pk_w    = (const float*)d_in[4];
    const float* pk_b    = (const float*)d_in[5];
    const float* pv_w    = (const float*)d_in[6];
    const float* pv_b    = (const float*)d_in[7];
    const float* merge_w = (const float*)d_in[8];
    const float* merge_b = (const float*)d_in[9];
    const float* mlp1_w  = (const float*)d_in[10];
    const float* mlp1_b  = (const float*)d_in[11];
    const float* bn_g    = (const float*)d_in[12];
    const float* bn_b    = (const float*)d_in[13];
    const float* mlp2_w  = (const float*)d_in[14];
    const float* mlp2_b  = (const float*)d_in[15];
    float* out = (float*)d_out;

    __nv_bfloat16 *Qp, *Kp, *Vp, *Ap, *mhip, *mlop, *xhip, *xlop;
    __nv_bfloat16 *wq, *wk, *wv, *wm, *w1h, *w1l, *w2h, *w2l;
    float *Hp, *scalep, *shiftp;
    cudaGetSymbolAddress((void**)&Qp,     g_Q);
    cudaGetSymbolAddress((void**)&Kp,     g_K);
    cudaGetSymbolAddress((void**)&Vp,     g_V);
    cudaGetSymbolAddress((void**)&Ap,     g_attn);
    cudaGetSymbolAddress((void**)&mhip,   g_msghi);
    cudaGetSymbolAddress((void**)&mlop,   g_msglo);
    cudaGetSymbolAddress((void**)&xhip,   g_xhi);
    cudaGetSymbolAddress((void**)&xlop,   g_xlo);
    cudaGetSymbolAddress((void**)&Hp,     g_h);
    cudaGetSymbolAddress((void**)&scalep, g_scale);
    cudaGetSymbolAddress((void**)&shiftp, g_shift);
    cudaGetSymbolAddress((void**)&wq,     g_wq);
    cudaGetSymbolAddress((void**)&wk,     g_wk);
    cudaGetSymbolAddress((void**)&wv,     g_wv);
    cudaGetSymbolAddress((void**)&wm,     g_wm);
    cudaGetSymbolAddress((void**)&w1h,    g_w1hi);
    cudaGetSymbolAddress((void**)&w1l,    g_w1lo);
    cudaGetSymbolAddress((void**)&w2h,    g_w2hi);
    cudaGetSymbolAddress((void**)&w2l,    g_w2lo);

    cudaFuncSetAttribute(flash_attn_bf16,
                         cudaFuncAttributeMaxDynamicSharedMemorySize, FA_DSM);

    dim3 blk(256);
    dim3 g256(NPTS / 128, D_MODEL / 128, NB);
    dim3 g512(NPTS / 128, TWO_D / 128, NB);

    const float qsc = 0.125f * L2E;

    // ---- converters: ONE weight kernel + one x-split
    cvt_weights_kernel<<<640, blk>>>(pq_w, pk_w, pv_w, merge_w, mlp1_w, mlp2_w,
                                     wq, wk, wv, wm, w1h, w1l, w2h, w2l);
    const int xn4 = NB * D_MODEL * NPTS / 4;
    split_bf16_kernel<<<xn4 / 256, blk>>>(x, xhip, xlop, xn4);

    // ---- Q/K/V projections (bf16 W, fp32 X, bf16 out; Q pre-scaled)
    gemm_bf16<<<g256, blk>>>(x,   wq, pq_b, Qp, nullptr, D_MODEL, D_MODEL, 0, 0, 1, qsc);
    gemm_bf16<<<g256, blk>>>(src, wk, pk_b, Kp, nullptr, D_MODEL, D_MODEL, 0, 0, 1, 1.0f);
    gemm_bf16<<<g256, blk>>>(src, wv, pv_b, Vp, nullptr, D_MODEL, D_MODEL, 0, 0, 1, 1.0f);

    // ---- multi-head attention (Schraudolph softmax)
    flash_attn_bf16<<<dim3(NPTS / 128, HEADS, NB), dim3(128), FA_DSM>>>(Qp, Kp, Vp, Ap);

    // ---- merge: bf16 in (permuted rows), output split hi/lo for mlp1
    gemm_bf16<<<g256, blk>>>(Ap, wm, merge_b, mhip, mlop, D_MODEL, D_MODEL, 1, 1, 2, 1.0f);

    // ---- mlp1 on concat([x, message]) — pre-split inputs, raw copies
    gemm_bf16_hp<<<g512, blk>>>(w1h, w1l, xhip, xlop, mhip, mlop, nullptr,
                                mlp1_b, nullptr, nullptr,
                                Hp, D_MODEL, D_MODEL, TWO_D, 0);

    // ---- BN stats -> affine
    bn_stats_kernel<<<TWO_D, 256>>>(Hp, bn_g, bn_b, scalep, shiftp);

    // ---- mlp2 with fused BN affine + ReLU (fp32 X path)
    gemm_bf16_hp<<<g256, blk>>>(w2h, w2l, nullptr, nullptr, nullptr, nullptr, Hp,
                                mlp2_b, scalep, shiftp,
                                out, TWO_D, 0, D_MODEL, 1);
}